// round 15
// baseline (speedup 1.0000x reference)
#include <cuda_runtime.h>
#include <cuda_fp16.h>
#include <math.h>
#include <stdint.h>

#define NTRK 4096
#define NVID 512

// ------------------------- device scratch (no runtime allocation) -------------------------
__device__ unsigned g_W1f[88 * 128];            // conv1 W packed [kp][co], k = kt*56+ci (K=176)
__device__ unsigned g_W2h[192 * 128];           // conv2 W packed [kp][co], k = kt*128+ci
__device__ unsigned g_Wihh[64 * 384];           // gru_wih^T packed [kp][3H]
__device__ unsigned g_WhhH[64 * 384];           // gru_whh^T packed [kp][3H]
__device__ float    g_bgi[384];                 // bih (+bhh for r,z)
__device__ unsigned g_WhandH[512 * 128];        // folded img_w@hand_w packed [kp][n]
__device__ float    g_bhand[128];               // folded img_b @ hand_w + hand_b
__device__ unsigned g_fc1h[128 * 256];          // fc1 W packed [kp][j]
__device__ unsigned g_X2h[NTRK * 32 * 64];      // conv2 out packed [131072][64w]
__device__ unsigned g_trackH[NTRK * 128];       // [kp_feat | hand_feat] packed [4096][128w]
__device__ float    g_H1[NTRK * 256];           // fc1 out fp32
__device__ unsigned g_vmax[NVID];               // ordered-encoded segment max

// ------------------------- streams/events for graph fork-join (created once, pre-baseline) --
static cudaStream_t g_sB;
static cudaEvent_t g_evF, g_evJ;
namespace {
struct StreamInit {
    StreamInit() {
        cudaStreamCreate(&g_sB);
        cudaEventCreateWithFlags(&g_evF, cudaEventDisableTiming);
        cudaEventCreateWithFlags(&g_evJ, cudaEventDisableTiming);
    }
} s_streamInit;
}

// ------------------------- helpers -------------------------
__device__ __forceinline__ unsigned f2ord(float f) {
    unsigned u = __float_as_uint(f);
    return (u & 0x80000000u) ? ~u : (u | 0x80000000u);
}
__device__ __forceinline__ float ord2f(unsigned u) {
    return __uint_as_float((u & 0x80000000u) ? (u & 0x7fffffffu) : ~u);
}
__device__ __forceinline__ unsigned su32(const void* p) {
    unsigned r;
    asm("{.reg .u64 t; cvta.to.shared.u64 t, %1; cvt.u32.u64 %0, t;}" : "=r"(r) : "l"(p));
    return r;
}
__device__ __forceinline__ void cpa16(unsigned d, const void* s) {
    asm volatile("cp.async.cg.shared.global [%0],[%1],16;" :: "r"(d), "l"(s));
}
__device__ __forceinline__ void cpcommit() { asm volatile("cp.async.commit_group;"); }
__device__ __forceinline__ void cpwait0() { asm volatile("cp.async.wait_group 0;"); }
__device__ __forceinline__ void cpwait1() { asm volatile("cp.async.wait_group 1;"); }
__device__ __forceinline__ void mma16h(float* d, const unsigned* a, const unsigned* b) {
    asm volatile(
        "mma.sync.aligned.m16n8k16.row.col.f32.f16.f16.f32 "
        "{%0,%1,%2,%3},{%4,%5,%6,%7},{%8,%9},{%0,%1,%2,%3};"
        : "+f"(d[0]), "+f"(d[1]), "+f"(d[2]), "+f"(d[3])
        : "r"(a[0]), "r"(a[1]), "r"(a[2]), "r"(a[3]), "r"(b[0]), "r"(b[1]));
}
__device__ __forceinline__ unsigned packh2(float lo, float hi) {
    __half2 h = __floats2half2_rn(lo, hi);
    return *reinterpret_cast<unsigned*>(&h);
}
__device__ __forceinline__ float2 unpackh2(unsigned w) {
    return __half22float2(*reinterpret_cast<__half2*>(&w));
}
__device__ __forceinline__ float sigm(float x) { return 1.f / (1.f + __expf(-x)); }

// ------------------------- prep: weight packing only -------------------------
__global__ void prep1(const float* __restrict__ c1w, const float* __restrict__ c2w,
                      const float* __restrict__ wih, const float* __restrict__ whh,
                      const float* __restrict__ bih, const float* __restrict__ bhh,
                      const float* __restrict__ fc1w) {
    const long total = 11264 + 24576 + 24576 + 24576 + 384 + 32768 + NVID;
    for (long i = (long)blockIdx.x * blockDim.x + threadIdx.x; i < total;
         i += (long)gridDim.x * blockDim.x) {
        long idx = i;
        if (idx < 11264) {  // W1f [kp][co], k = kt*56+ci (pose rows padded to 56 halves)
            int kp = (int)(idx >> 7), co = (int)(idx & 127);
            float v[2];
#pragma unroll
            for (int e = 0; e < 2; e++) {
                int k = 2 * kp + e;
                int kt = k / 56, ci = k % 56;
                v[e] = (kt < 3 && ci < 51) ? c1w[co * 153 + ci * 3 + kt] : 0.f;
            }
            g_W1f[idx] = packh2(v[0], v[1]);
            continue;
        }
        idx -= 11264;
        if (idx < 24576) {  // W2h [kp][co], k = kt*128+ci
            int kp = (int)(idx >> 7), co = (int)(idx & 127);
            float v[2];
#pragma unroll
            for (int e = 0; e < 2; e++) {
                int k = 2 * kp + e;
                int kt = k >> 7, ci = k & 127;
                v[e] = c2w[co * 384 + ci * 3 + kt];
            }
            g_W2h[idx] = packh2(v[0], v[1]);
            continue;
        }
        idx -= 24576;
        if (idx < 24576) {  // Wihh [kp][j]
            int kp = (int)(idx / 384), j = (int)(idx % 384);
            g_Wihh[idx] = packh2(wih[j * 128 + 2 * kp], wih[j * 128 + 2 * kp + 1]);
            continue;
        }
        idx -= 24576;
        if (idx < 24576) {  // WhhH [kp][j]
            int kp = (int)(idx / 384), j = (int)(idx % 384);
            g_WhhH[idx] = packh2(whh[j * 128 + 2 * kp], whh[j * 128 + 2 * kp + 1]);
            continue;
        }
        idx -= 24576;
        if (idx < 384) { g_bgi[idx] = bih[idx] + ((idx < 256) ? bhh[idx] : 0.f); continue; }
        idx -= 384;
        if (idx < 32768) {  // fc1h [kp][j]
            int kp = (int)(idx >> 8), j = (int)(idx & 255);
            g_fc1h[idx] = packh2(fc1w[(2 * kp) * 256 + j], fc1w[(2 * kp + 1) * 256 + j]);
            continue;
        }
        idx -= 32768;
        g_vmax[idx] = 0u;
    }
}

// ------------------------- fold img_w @ hand_w -> half2-packed [kp][n] -------------------------
__global__ void __launch_bounds__(256) foldw(const float* __restrict__ img_w,
                                             const float* __restrict__ img_b,
                                             const float* __restrict__ hand_w,
                                             const float* __restrict__ hand_b) {
    __shared__ float simg[64][68];
    __shared__ float shw[64][132];
    __shared__ float sv[512];
    int b = blockIdx.x, tid = threadIdx.x;
    if (b < 16) {
        int tr = tid >> 4;
        int tc = (tid & 15) * 8;
        float acc[4][8];
#pragma unroll
        for (int i = 0; i < 4; i++)
#pragma unroll
            for (int j = 0; j < 8; j++) acc[i][j] = 0.f;
        for (int kt = 0; kt < 512; kt += 64) {
            __syncthreads();
#pragma unroll
            for (int i = 0; i < 4; i++) {
                int ch = tid + i * 256;
                int r = ch >> 4, c4 = (ch & 15) * 4;
                *(float4*)&simg[r][c4] = *(const float4*)&img_w[(long)(b * 64 + r) * 512 + kt + c4];
            }
#pragma unroll
            for (int i = 0; i < 8; i++) {
                int ch = tid + i * 256;
                int r = ch >> 5, c4 = (ch & 31) * 4;
                *(float4*)&shw[r][c4] = *(const float4*)&hand_w[(long)(kt + r) * 128 + c4];
            }
            __syncthreads();
#pragma unroll 8
            for (int q = 0; q < 64; q++) {
                float4 w0 = *(float4*)&shw[q][tc];
                float4 w1 = *(float4*)&shw[q][tc + 4];
#pragma unroll
                for (int i = 0; i < 4; i++) {
                    float a = simg[tr * 4 + i][q];
                    acc[i][0] += a * w0.x; acc[i][1] += a * w0.y;
                    acc[i][2] += a * w0.z; acc[i][3] += a * w0.w;
                    acc[i][4] += a * w1.x; acc[i][5] += a * w1.y;
                    acc[i][6] += a * w1.z; acc[i][7] += a * w1.w;
                }
            }
        }
        int kp0 = (b * 64 + tr * 4) >> 1;
#pragma unroll
        for (int j = 0; j < 8; j++) {
            g_WhandH[(kp0) * 128 + tc + j]     = packh2(acc[0][j], acc[1][j]);
            g_WhandH[(kp0 + 1) * 128 + tc + j] = packh2(acc[2][j], acc[3][j]);
        }
    } else {
        for (int q = tid; q < 512; q += 256) sv[q] = img_b[q];
        __syncthreads();
        if (tid < 128) {
            float a = hand_b[tid];
#pragma unroll 8
            for (int q = 0; q < 512; q++) a += sv[q] * hand_w[q * 128 + tid];
            g_bhand[tid] = a;
        }
    }
}

// ------------------------- fused pose-chain convs: im2col+conv1+conv2, 4 tracks/block --------
// smem (words): sP 3816 | sW1 88*136 | sW2 192*136 | sX1 4*34*64 | sb1 128 | sb2 128
#define CF_PW 28
#define CF_PSZ (4 * 34 * CF_PW + 8)
#define CF_WST 136
#define CF_X1SZ (4 * 34 * 64)
#define CF_TOTW (CF_PSZ + 88 * CF_WST + 192 * CF_WST + CF_X1SZ + 256)
#define CF_SMEM (CF_TOTW * 4)

__global__ void __launch_bounds__(256) convf(
    const float* __restrict__ poses,
    const unsigned* __restrict__ W1f, const unsigned* __restrict__ W2h,
    const float* __restrict__ c1b, const float* __restrict__ c2b,
    unsigned* __restrict__ x2h) {
    extern __shared__ unsigned smc[];
    unsigned* sP = smc;
    unsigned* sW1 = smc + CF_PSZ;
    unsigned* sW2 = sW1 + 88 * CF_WST;
    unsigned* sX1 = sW2 + 192 * CF_WST;
    float* sb1 = (float*)(sX1 + CF_X1SZ);
    float* sb2 = sb1 + 128;

    const int tid = threadIdx.x, lane = tid & 31, wid = tid >> 5;
    const int wm = wid & 3, wn = wid >> 2, g = lane >> 2, t2 = lane & 3;
    const long b = blockIdx.x;

    // weights via cp.async (L2-resident across blocks)
    {
        unsigned d1 = su32(sW1);
#pragma unroll
        for (int i = 0; i < 11; i++) {
            int ch = tid + i * 256;
            int row = ch >> 5, c4 = (ch & 31) * 4;
            cpa16(d1 + (unsigned)((row * CF_WST + c4) * 4), W1f + row * 128 + c4);
        }
        unsigned d2 = su32(sW2);
#pragma unroll
        for (int i = 0; i < 24; i++) {
            int ch = tid + i * 256;
            int row = ch >> 5, c4 = (ch & 31) * 4;
            cpa16(d2 + (unsigned)((row * CF_WST + c4) * 4), W2h + row * 128 + c4);
        }
        cpcommit();
    }
    if (tid < 128) { sb1[tid] = c1b[tid]; sb2[tid] = c2b[tid]; }
    // pose tile: fp16 [4 tracks][34 padded rows][28 words]; rows 0,33 zero; halves >=51 zero
    for (int idx = tid; idx < 4 * 34 * CF_PW; idx += 256) {
        int tr = idx / (34 * CF_PW), r2 = idx % (34 * CF_PW);
        int tp = r2 / CF_PW, wi = r2 % CF_PW;
        unsigned wv = 0u;
        if (tp >= 1 && tp <= 32) {
            float v0 = 0.f, v1 = 0.f;
            int ci = wi * 2;
            const float* pr = poses + ((b * 4 + tr) * 32 + tp - 1) * 51;
            if (ci < 51) v0 = pr[ci];
            if (ci + 1 < 51) v1 = pr[ci + 1];
            wv = packh2(v0, v1);
        }
        sP[idx] = wv;
    }
    if (tid < 8) sP[4 * 34 * CF_PW + tid] = 0u;
    // zero X1 pad rows (tp=0 and 33 per track)
    for (int i = tid; i < 512; i += 256) {
        int rr = i >> 6, wc = i & 63;
        int tr = rr >> 1, tp = (rr & 1) ? 33 : 0;
        sX1[(tr * 34 + tp) * 64 + wc] = 0u;
    }
    cpwait0();
    __syncthreads();

    // per-thread M-row variants (v = i*2+h): row = wm*32 + v*8 + g
    int trv[4], tvv[4], pB[4];
#pragma unroll
    for (int v = 0; v < 4; v++) {
        int r = wm * 32 + v * 8 + g;
        trv[v] = r >> 5;
        tvv[v] = r & 31;
        pB[v] = (trv[v] * 34 + tvv[v]) * CF_PW;
    }

    float acc[2][8][4];
#pragma unroll
    for (int i = 0; i < 2; i++)
#pragma unroll
        for (int j = 0; j < 8; j++)
#pragma unroll
            for (int q = 0; q < 4; q++) acc[i][j][q] = 0.f;

    // ---- conv1: K=176 halves = 11 k-steps ----
#pragma unroll
    for (int s = 0; s < 11; s++) {
        int kc = s * 8 + t2;
        unsigned af[2][4];
#pragma unroll
        for (int i = 0; i < 2; i++) {
            af[i][0] = sP[pB[2 * i] + kc];
            af[i][1] = sP[pB[2 * i + 1] + kc];
            af[i][2] = sP[pB[2 * i] + kc + 4];
            af[i][3] = sP[pB[2 * i + 1] + kc + 4];
        }
#pragma unroll
        for (int j = 0; j < 8; j++) {
            int bc = wn * 64 + j * 8 + g;
            unsigned bf[2];
            bf[0] = sW1[kc * CF_WST + bc];
            bf[1] = sW1[(kc + 4) * CF_WST + bc];
            mma16h(acc[0][j], af[0], bf);
            mma16h(acc[1][j], af[1], bf);
        }
    }
    // epilogue conv1 -> sX1 (XOR-swizzled words)
#pragma unroll
    for (int i = 0; i < 2; i++)
#pragma unroll
        for (int j = 0; j < 8; j++)
#pragma unroll
            for (int h = 0; h < 2; h++) {
                int v = i * 2 + h;
                int srow = trv[v] * 34 + tvv[v] + 1;
                int col = wn * 64 + j * 8 + t2 * 2;
                float v0 = fmaxf(acc[i][j][h * 2] + sb1[col], 0.f);
                float v1 = fmaxf(acc[i][j][h * 2 + 1] + sb1[col + 1], 0.f);
                int wc = col >> 1;
                sX1[srow * 64 + (wc ^ ((srow & 7) << 2))] = packh2(v0, v1);
            }
    __syncthreads();

    // ---- conv2: K=384 halves = 24 k-steps over 3-row halo ----
#pragma unroll
    for (int i = 0; i < 2; i++)
#pragma unroll
        for (int j = 0; j < 8; j++)
#pragma unroll
            for (int q = 0; q < 4; q++) acc[i][j][q] = 0.f;

#pragma unroll
    for (int s = 0; s < 24; s++) {
        int kc = s * 8 + t2;
        int off = kc >> 6, cw = kc & 63;   // cw+4 stays within the 64-block
        unsigned af[2][4];
#pragma unroll
        for (int i = 0; i < 2; i++) {
            int sr0 = trv[2 * i] * 34 + tvv[2 * i] + off;
            int sr1 = trv[2 * i + 1] * 34 + tvv[2 * i + 1] + off;
            int sw0 = (sr0 & 7) << 2, sw1 = (sr1 & 7) << 2;
            af[i][0] = sX1[sr0 * 64 + (cw ^ sw0)];
            af[i][1] = sX1[sr1 * 64 + (cw ^ sw1)];
            af[i][2] = sX1[sr0 * 64 + ((cw + 4) ^ sw0)];
            af[i][3] = sX1[sr1 * 64 + ((cw + 4) ^ sw1)];
        }
#pragma unroll
        for (int j = 0; j < 8; j++) {
            int bc = wn * 64 + j * 8 + g;
            unsigned bf[2];
            bf[0] = sW2[kc * CF_WST + bc];
            bf[1] = sW2[(kc + 4) * CF_WST + bc];
            mma16h(acc[0][j], af[0], bf);
            mma16h(acc[1][j], af[1], bf);
        }
    }
    // epilogue conv2 -> X2h global
#pragma unroll
    for (int i = 0; i < 2; i++)
#pragma unroll
        for (int j = 0; j < 8; j++)
#pragma unroll
            for (int h = 0; h < 2; h++) {
                int v = i * 2 + h;
                int col = wn * 64 + j * 8 + t2 * 2;
                float v0 = fmaxf(acc[i][j][h * 2] + sb2[col], 0.f);
                float v1 = fmaxf(acc[i][j][h * 2 + 1] + sb2[col + 1], 0.f);
                long grow = b * 128 + (wm * 32 + v * 8 + g);
                x2h[grow * 64 + (col >> 1)] = packh2(v0, v1);
            }
}

// ------------------------- unified fp16 GEMM (fc1 only) -------------------------
template <int ARPG, int ORPG, int MODE, bool RELU>
__global__ void __launch_bounds__(256) gemm_h(
    const unsigned* __restrict__ A, long aGS, long aRS, long aOfs,
    const unsigned* __restrict__ Bm, int ldb,
    const float* __restrict__ bias,
    void* __restrict__ CoutV, long oGS, long oRS, long oOfs,
    int K) {
    constexpr int SAST = 20, SBST = 136;
    constexpr int ASZ = 128 * SAST, BSZ = 16 * SBST;
    extern __shared__ unsigned smu[];
    unsigned* sA = smu;
    unsigned* sB = smu + 2 * ASZ;

    const int tid = threadIdx.x, lane = tid & 31, wid = tid >> 5;
    const int wm = wid & 3, wn = wid >> 2;
    const int g = lane >> 2, t2 = lane & 3;
    const long m0 = (long)blockIdx.x * 128;
    const int n0 = blockIdx.y * 128;

    float acc[2][8][4];
#pragma unroll
    for (int i = 0; i < 2; i++)
#pragma unroll
        for (int j = 0; j < 8; j++)
#pragma unroll
            for (int q = 0; q < 4; q++) acc[i][j][q] = 0.f;

    const unsigned* aP[2];
    unsigned aD[2];
#pragma unroll
    for (int i = 0; i < 2; i++) {
        int ch = tid + i * 256;
        int row = ch >> 2, cw = (ch & 3) * 4;
        long gr = m0 + row;
        const unsigned* rp = ARPG ? (A + (gr / ARPG) * aGS + (gr % ARPG) * aRS + aOfs)
                                  : (A + gr * aRS + aOfs);
        aP[i] = rp + cw;
        aD[i] = su32(sA) + (unsigned)((row * SAST + cw) * 4);
    }
    const unsigned* bP[2];
    unsigned bD[2];
#pragma unroll
    for (int i = 0; i < 2; i++) {
        int ch = tid + i * 256;
        int row = ch >> 5, cw = (ch & 31) * 4;
        bP[i] = Bm + (long)row * ldb + n0 + cw;
        bD[i] = su32(sB) + (unsigned)((row * SBST + cw) * 4);
    }

    auto load = [&](int buf, int s) {
#pragma unroll
        for (int i = 0; i < 2; i++) cpa16(aD[i] + (unsigned)buf * ASZ * 4, aP[i] + s * 16);
#pragma unroll
        for (int i = 0; i < 2; i++) cpa16(bD[i] + (unsigned)buf * BSZ * 4, bP[i] + (long)s * 16 * ldb);
        cpcommit();
    };

    const int NS = K / 32;
    load(0, 0);
    for (int s = 0; s < NS; s++) {
        if (s + 1 < NS) { load((s + 1) & 1, s + 1); cpwait1(); }
        else cpwait0();
        __syncthreads();
        const unsigned* cA = sA + (s & 1) * ASZ;
        const unsigned* cB = sB + (s & 1) * BSZ;
#pragma unroll
        for (int kk2 = 0; kk2 < 2; kk2++) {
            unsigned af[2][4];
            const int r0 = wm * 32 + g, kc = kk2 * 8 + t2;
#pragma unroll
            for (int i = 0; i < 2; i++) {
                af[i][0] = cA[(r0 + i * 16) * SAST + kc];
                af[i][1] = cA[(r0 + i * 16 + 8) * SAST + kc];
                af[i][2] = cA[(r0 + i * 16) * SAST + kc + 4];
                af[i][3] = cA[(r0 + i * 16 + 8) * SAST + kc + 4];
            }
#pragma unroll
            for (int j = 0; j < 8; j++) {
                unsigned bf[2];
                int bc = wn * 64 + j * 8 + g;
                bf[0] = cB[kc * SBST + bc];
                bf[1] = cB[(kc + 4) * SBST + bc];
                mma16h(acc[0][j], af[0], bf);
                mma16h(acc[1][j], af[1], bf);
            }
        }
        __syncthreads();
    }

#pragma unroll
    for (int i = 0; i < 2; i++)
#pragma unroll
        for (int j = 0; j < 8; j++)
#pragma unroll
            for (int h = 0; h < 2; h++) {
                long gr = m0 + wm * 32 + i * 16 + h * 8 + g;
                int col = n0 + wn * 64 + j * 8 + t2 * 2;
                float v0 = acc[i][j][h * 2 + 0] + bias[col];
                float v1 = acc[i][j][h * 2 + 1] + bias[col + 1];
                if (RELU) { v0 = fmaxf(v0, 0.f); v1 = fmaxf(v1, 0.f); }
                if (MODE == 0) {
                    float* O = (float*)CoutV;
                    float* op = ORPG ? (O + (gr / ORPG) * oGS + (gr % ORPG) * oRS + oOfs + col)
                                     : (O + gr * oRS + oOfs + col);
                    ((float2*)op)[0] = make_float2(v0, v1);
                } else {
                    unsigned* O = (unsigned*)CoutV;
                    int wc = col >> 1;
                    unsigned* op = ORPG ? (O + (gr / ORPG) * oGS + (gr % ORPG) * oRS + oOfs + wc)
                                        : (O + gr * oRS + oOfs + wc);
                    *op = packh2(v0, v1);
                }
            }
}

// ------------------------- hand GEMM: EXACT R10 configuration (do not touch) ----------------
#define HH_SAST 40
#define HH_SBST 136
#define HH_ASZ  (128 * HH_SAST)
#define HH_BSZ  (16 * HH_SBST)
#define HH_SMEM ((2 * HH_ASZ + 2 * HH_BSZ + 4 * 132) * 4)

__global__ void __launch_bounds__(256) hand_h(
    const float* __restrict__ hands,
    const unsigned* __restrict__ Bh,
    const float* __restrict__ bias,
    unsigned* __restrict__ trackH) {
    extern __shared__ float sm[];
    float* sA = sm;
    unsigned* sB = (unsigned*)(sm + 2 * HH_ASZ);
    float* mst = sm + 2 * HH_ASZ + 2 * HH_BSZ;

    const int tid = threadIdx.x, lane = tid & 31, wid = tid >> 5;
    const int wm = wid & 3, wn = wid >> 2;
    const long m0 = (long)blockIdx.x * 128;
    const int g = lane >> 2, t2 = lane & 3;

    float acc[2][8][4];
#pragma unroll
    for (int i = 0; i < 2; i++)
#pragma unroll
        for (int j = 0; j < 8; j++)
#pragma unroll
            for (int q = 0; q < 4; q++) acc[i][j][q] = 0.f;

    const float* aP[4];
    unsigned aD[4];
#pragma unroll
    for (int i = 0; i < 4; i++) {
        int ch = tid + i * 256;
        int row = ch >> 3, c4 = (ch & 7) * 4;
        aP[i] = hands + (m0 + row) * 1024 + c4;
        aD[i] = su32(sA) + (unsigned)((row * HH_SAST + c4) * 4);
    }
    const unsigned* bP[2];
    unsigned bD[2];
#pragma unroll
    for (int i = 0; i < 2; i++) {
        int ch = tid + i * 256;
        int row = ch >> 5, c4 = (ch & 31) * 4;
        bP[i] = Bh + row * 128 + c4;
        bD[i] = su32(sB) + (unsigned)((row * HH_SBST + c4) * 4);
    }

    auto load = [&](int buf, int s) {
#pragma unroll
        for (int i = 0; i < 4; i++) cpa16(aD[i] + (unsigned)buf * HH_ASZ * 4, aP[i] + s * 32);
#pragma unroll
        for (int i = 0; i < 2; i++) cpa16(bD[i] + (unsigned)buf * HH_BSZ * 4, bP[i] + s * 16 * 128);
        cpcommit();
    };

    load(0, 0);
    for (int s = 0; s < 32; s++) {
        if (s + 1 < 32) { load((s + 1) & 1, s + 1); cpwait1(); }
        else cpwait0();
        __syncthreads();
        const float* cA = sA + (s & 1) * HH_ASZ;
        const unsigned* cB = sB + (s & 1) * HH_BSZ;
#pragma unroll
        for (int kk2 = 0; kk2 < 2; kk2++) {
            const int c = kk2 * 16 + t2 * 2;
            unsigned af[2][4];
#pragma unroll
            for (int i = 0; i < 2; i++) {
                int r = wm * 32 + g + i * 16;
                float2 v0 = *(const float2*)(cA + r * HH_SAST + c);
                float2 v1 = *(const float2*)(cA + (r + 8) * HH_SAST + c);
                float2 v2 = *(const float2*)(cA + r * HH_SAST + c + 8);
                float2 v3 = *(const float2*)(cA + (r + 8) * HH_SAST + c + 8);
                af[i][0] = packh2(v0.x, v0.y);
                af[i][1] = packh2(v1.x, v1.y);
                af[i][2] = packh2(v2.x, v2.y);
                af[i][3] = packh2(v3.x, v3.y);
            }
            const int kp0 = kk2 * 8 + t2;
            const int bc = wn * 64 + g;
#pragma unroll
            for (int j = 0; j < 8; j++) {
                unsigned bf[2];
                bf[0] = cB[kp0 * HH_SBST + bc + j * 8];
                bf[1] = cB[(kp0 + 4) * HH_SBST + bc + j * 8];
                mma16h(acc[0][j], af[0], bf);
                mma16h(acc[1][j], af[1], bf);
            }
        }
        __syncthreads();
    }

    float mc[8][2];
#pragma unroll
    for (int j = 0; j < 8; j++) {
        mc[j][0] = fmaxf(fmaxf(acc[0][j][0], acc[0][j][2]), fmaxf(acc[1][j][0], acc[1][j][2]));
        mc[j][1] = fmaxf(fmaxf(acc[0][j][1], acc[0][j][3]), fmaxf(acc[1][j][1], acc[1][j][3]));
    }
#pragma unroll
    for (int ofs = 4; ofs < 32; ofs <<= 1)
#pragma unroll
        for (int j = 0; j < 8; j++) {
            mc[j][0] = fmaxf(mc[j][0], __shfl_xor_sync(0xffffffffu, mc[j][0], ofs));
            mc[j][1] = fmaxf(mc[j][1], __shfl_xor_sync(0xffffffffu, mc[j][1], ofs));
        }
    if (lane < 4) {
#pragma unroll
        for (int j = 0; j < 8; j++) {
            int col = wn * 64 + j * 8 + lane * 2;
            mst[wm * 132 + col] = mc[j][0];
            mst[wm * 132 + col + 1] = mc[j][1];
        }
    }
    __syncthreads();
    {
        int sub = tid & 127;
        if (sub < 64) {
            int trk2 = tid >> 7, wc = sub;
            float v0 = fmaxf(mst[(trk2 * 2) * 132 + 2 * wc], mst[(trk2 * 2 + 1) * 132 + 2 * wc]);
            float v1 = fmaxf(mst[(trk2 * 2) * 132 + 2 * wc + 1], mst[(trk2 * 2 + 1) * 132 + 2 * wc + 1]);
            long track = (long)blockIdx.x * 2 + trk2;
            trackH[track * 128 + 64 + wc] = packh2(v0 + bias[2 * wc], v1 + bias[2 * wc + 1]);
        }
    }
}

// ------------------------- fused GRU+gi: Whh AND Wih resident, x_t streamed, 1 launch --------
#define GR_WST 392
#define GR_HST 68
#define GR_SMEM ((2 * 64 * GR_WST + 3 * 32 * GR_HST) * 4)

__global__ void __launch_bounds__(256) gru_fused(
    const unsigned* __restrict__ whhH,
    const unsigned* __restrict__ wihH,
    const unsigned* __restrict__ x2h,
    const float* __restrict__ bgi,
    const float* __restrict__ bhhn,
    unsigned* __restrict__ trackH) {
    extern __shared__ unsigned smg[];
    unsigned* sWhh = smg;
    unsigned* sWih = smg + 64 * GR_WST;
    unsigned* sh   = smg + 2 * 64 * GR_WST;
    unsigned* sx   = sh + 32 * GR_HST;
    const int tid = threadIdx.x, lane = tid & 31, w = tid >> 5;
    const int m0 = blockIdx.x * 32;
    const int g = lane >> 2, t2 = lane & 3, cb = t2 * 2;

    {
        unsigned b1 = su32(sWhh), b2 = su32(sWih);
#pragma unroll
        for (int i = 0; i < 24; i++) {
            int ch = tid + i * 256;
            int row = ch / 96, cx = (ch % 96) * 4;
            cpa16(b1 + (unsigned)((row * GR_WST + cx) * 4), whhH + row * 384 + cx);
            cpa16(b2 + (unsigned)((row * GR_WST + cx) * 4), wihH + row * 384 + cx);
        }
#pragma unroll
        for (int i = 0; i < 2; i++) {
            int ch = tid + i * 256;
            int row = ch >> 4, c4 = (ch & 15) * 4;
            cpa16(su32(sx) + (unsigned)((row * GR_HST + c4) * 4),
                  x2h + ((long)(m0 + row) * 32) * 64 + c4);
        }
        cpcommit();
    }
    for (int i = tid; i < 32 * GR_HST; i += 256) sh[i] = 0u;
    cpwait0();
    __syncthreads();

    float br[2][2], bz[2][2], bni[2][2], bn[2][2];
#pragma unroll
    for (int jj = 0; jj < 2; jj++) {
        int c = w * 16 + jj * 8 + cb;
        br[jj][0] = bgi[c];        br[jj][1] = bgi[c + 1];
        bz[jj][0] = bgi[128 + c];  bz[jj][1] = bgi[128 + c + 1];
        bni[jj][0] = bgi[256 + c]; bni[jj][1] = bgi[256 + c + 1];
        bn[jj][0] = bhhn[c];       bn[jj][1] = bhhn[c + 1];
    }

    for (int step = 0; step < 32; step++) {
        if (step < 31) {
            unsigned dst = su32(sx) + (unsigned)(((step + 1) & 1) * 32 * GR_HST * 4);
#pragma unroll
            for (int i = 0; i < 2; i++) {
                int ch = tid + i * 256;
                int row = ch >> 4, c4 = (ch & 15) * 4;
                cpa16(dst + (unsigned)((row * GR_HST + c4) * 4),
                      x2h + ((long)(m0 + row) * 32 + step + 1) * 64 + c4);
            }
            cpcommit();
        }
        float acc[8][2][4];
#pragma unroll
        for (int f = 0; f < 8; f++)
#pragma unroll
            for (int i = 0; i < 2; i++)
#pragma unroll
                for (int q = 0; q < 4; q++) acc[f][i][q] = 0.f;

        const unsigned* cx = sx + (step & 1) * 32 * GR_HST;
#pragma unroll
        for (int ch = 0; ch < 8; ch++) {
            unsigned afh[2][4], afx[2][4];
            const int kc = ch * 8 + t2;
#pragma unroll
            for (int i = 0; i < 2; i++) {
                int r = i * 16 + g;
                afh[i][0] = sh[r * GR_HST + kc];
                afh[i][1] = sh[(r + 8) * GR_HST + kc];
                afh[i][2] = sh[r * GR_HST + kc + 4];
                afh[i][3] = sh[(r + 8) * GR_HST + kc + 4];
                afx[i][0] = cx[r * GR_HST + kc];
                afx[i][1] = cx[(r + 8) * GR_HST + kc];
                afx[i][2] = cx[r * GR_HST + kc + 4];
                afx[i][3] = cx[(r + 8) * GR_HST + kc + 4];
            }
#pragma unroll
            for (int gg = 0; gg < 3; gg++)
#pragma unroll
                for (int jj = 0; jj < 2; jj++) {
                    int col = gg * 128 + w * 16 + jj * 8 + g;
                    unsigned bfh[2], bfx[2];
                    bfh[0] = sWhh[kc * GR_WST + col];
                    bfh[1] = sWhh[(kc + 4) * GR_WST + col];
                    bfx[0] = sWih[kc * GR_WST + col];
                    bfx[1] = sWih[(kc + 4) * GR_WST + col];
                    int hg = gg * 2 + jj;
                    int xg = (gg < 2) ? hg : (6 + jj);
                    mma16h(acc[hg][0], afh[0], bfh);
                    mma16h(acc[hg][1], afh[1], bfh);
                    mma16h(acc[xg][0], afx[0], bfx);
                    mma16h(acc[xg][1], afx[1], bfx);
                }
        }
        __syncthreads();

#pragma unroll
        for (int i = 0; i < 2; i++)
#pragma unroll
            for (int rh = 0; rh < 2; rh++) {
                int row = g + i * 16 + rh * 8;
                int q = rh * 2;
#pragma unroll
                for (int jj = 0; jj < 2; jj++) {
                    int wc = (w * 16 + jj * 8 + cb) >> 1;
                    float2 hold = unpackh2(sh[row * GR_HST + wc]);
                    float r0 = sigm(acc[jj][i][q] + br[jj][0]);
                    float r1 = sigm(acc[jj][i][q + 1] + br[jj][1]);
                    float z0 = sigm(acc[2 + jj][i][q] + bz[jj][0]);
                    float z1 = sigm(acc[2 + jj][i][q + 1] + bz[jj][1]);
                    float n0 = tanhf(acc[6 + jj][i][q] + bni[jj][0] + r0 * (acc[4 + jj][i][q] + bn[jj][0]));
                    float n1 = tanhf(acc[6 + jj][i][q + 1] + bni[jj][1] + r1 * (acc[4 + jj][i][q + 1] + bn[jj][1]));
                    float h0 = (1.f - z0) * n0 + z0 * hold.x;
                    float h1 = (1.f - z1) * n1 + z1 * hold.y;
                    sh[row * GR_HST + wc] = packh2(h0, h1);
                }
            }
        cpwait0();
        __syncthreads();
    }

#pragma unroll
    for (int it = 0; it < 8; it++) {
        int idx = it * 256 + tid;
        int row = idx >> 6, wc = idx & 63;
        trackH[(long)(m0 + row) * 128 + wc] = sh[row * GR_HST + wc];
    }
}

// ------------------------- small kernels -------------------------
__global__ void fc2seg(const float* __restrict__ w, const float* __restrict__ b2,
                       const int* __restrict__ vidx) {
    __shared__ float sw[256];
    int t = threadIdx.x;
    sw[t] = w[t];
    __syncthreads();
    int m = blockIdx.x * 256 + t;
    const float* h = &g_H1[(long)m * 256];
    float a = b2[0];
#pragma unroll 16
    for (int q = 0; q < 256; q++) a += h[q] * sw[q];
    atomicMax(&g_vmax[vidx[m]], f2ord(a));
}

__global__ void finalk(const float* __restrict__ nts, float* __restrict__ out) {
    int v = blockIdx.x * 256 + threadIdx.x;
    if (v < NVID) {
        unsigned u = g_vmax[v];
        float lg = (u == 0u) ? nts[0] : ord2f(u);
        out[v] = 1.f / (1.f + expf(-lg));
    }
}

// ------------------------- launch -------------------------
extern "C" void kernel_launch(void* const* d_in, const int* in_sizes, int n_in,
                              void* d_out, int out_size) {
    const float* poses  = (const float*)d_in[0];
    const float* hands  = (const float*)d_in[1];
    const int*   vidx   = (const int*)d_in[2];
    const float* c1w    = (const float*)d_in[3];
    const float* c1b    = (const float*)d_in[4];
    const float* c2w    = (const float*)d_in[5];
    const float* c2b    = (const float*)d_in[6];
    const float* wih    = (const float*)d_in[7];
    const float* whh    = (const float*)d_in[8];
    const float* bih    = (const float*)d_in[9];
    const float* bhh    = (const float*)d_in[10];
    const float* img_w  = (const float*)d_in[11];
    const float* img_b  = (const float*)d_in[12];
    const float* hand_w = (const float*)d_in[13];
    const float* hand_b = (const float*)d_in[14];
    const float* fc1w   = (const float*)d_in[15];
    const float* fc1b   = (const float*)d_in[16];
    const float* fc2w   = (const float*)d_in[17];
    const float* fc2b   = (const float*)d_in[18];
    const float* nts    = (const float*)d_in[19];
    float* out = (float*)d_out;

    unsigned *pW1f, *pW2h, *pWihh, *pWhhH, *pWhandH, *pfc1h, *pX2h, *pTrackH;
    float *pbgi, *pbhand, *pH1;
    cudaGetSymbolAddress((void**)&pW1f, g_W1f);
    cudaGetSymbolAddress((void**)&pW2h, g_W2h);
    cudaGetSymbolAddress((void**)&pWihh, g_Wihh);
    cudaGetSymbolAddress((void**)&pWhhH, g_WhhH);
    cudaGetSymbolAddress((void**)&pbgi, g_bgi);
    cudaGetSymbolAddress((void**)&pWhandH, g_WhandH);
    cudaGetSymbolAddress((void**)&pbhand, g_bhand);
    cudaGetSymbolAddress((void**)&pfc1h, g_fc1h);
    cudaGetSymbolAddress((void**)&pX2h, g_X2h);
    cudaGetSymbolAddress((void**)&pTrackH, g_trackH);
    cudaGetSymbolAddress((void**)&pH1, g_H1);

    constexpr int SM_H = (2 * 128 * 20 + 2 * 16 * 136) * 4;

    auto* kFc1 = gemm_h<0, 0, 0, true>;

    cudaFuncSetAttribute(kFc1, cudaFuncAttributeMaxDynamicSharedMemorySize, SM_H);
    cudaFuncSetAttribute(convf, cudaFuncAttributeMaxDynamicSharedMemorySize, CF_SMEM);
    cudaFuncSetAttribute(gru_fused, cudaFuncAttributeMaxDynamicSharedMemorySize, GR_SMEM);
    cudaFuncSetAttribute(hand_h, cudaFuncAttributeMaxDynamicSharedMemorySize, HH_SMEM);

    // ---- fork: hand path on g_sB, pose chain on default stream ----
    cudaEventRecord(g_evF, 0);
    cudaStreamWaitEvent(g_sB, g_evF, 0);

    foldw<<<17, 256, 0, g_sB>>>(img_w, img_b, hand_w, hand_b);
    hand_h<<<2048, 256, HH_SMEM, g_sB>>>(hands, pWhandH, pbhand, pTrackH);
    cudaEventRecord(g_evJ, g_sB);

    // default stream: weight prep -> fused convs -> fused GRU
    prep1<<<512, 256>>>(c1w, c2w, wih, whh, bih, bhh, fc1w);
    convf<<<1024, 256, CF_SMEM>>>(poses, pW1f, pW2h, c1b, c2b, pX2h);
    gru_fused<<<128, 256, GR_SMEM>>>(pWhhH, pWihh, pX2h, pbgi, bhh + 256, pTrackH);

    // ---- join, then scoring ----
    cudaStreamWaitEvent(0, g_evJ, 0);
    kFc1<<<dim3(32, 2), 256, SM_H>>>(pTrackH, 0, 128, 0, pfc1h, 256, fc1b,
                                     pH1, 0, 256, 0, 256);
    fc2seg<<<16, 256>>>(fc2w, fc2b, vidx);
    finalk<<<2, 256>>>(nts, out);
}

// round 16
// speedup vs baseline: 1.5454x; 1.5454x over previous
#include <cuda_runtime.h>
#include <cuda_fp16.h>
#include <math.h>
#include <stdint.h>

#define NTRK 4096
#define NVID 512

// ------------------------- device scratch (no runtime allocation) -------------------------
__device__ unsigned g_Ph[NTRK * 32 * 80];       // im2col(poses) fp16-packed [131072][80w] (K=160)
__device__ unsigned g_W1h[80 * 128];            // conv1 W packed [kp][co]
__device__ unsigned g_W2h[192 * 128];           // conv2 W packed [kp][co]
__device__ unsigned g_Wihh[64 * 384];           // gru_wih^T packed [kp][3H]
__device__ unsigned g_WhhH[64 * 384];           // gru_whh^T packed [kp][3H]
__device__ float    g_bgi[384];                 // bih (+bhh for r,z)
__device__ unsigned g_WhandH[512 * 128];        // folded img_w@hand_w packed [kp][n]
__device__ float    g_bhand[128];               // folded img_b @ hand_w + hand_b
__device__ unsigned g_fc1h[128 * 256];          // fc1 W packed [kp][j]
__device__ unsigned g_X1h[NTRK * 34 * 64];      // conv1 out packed, time-padded [n][34][64w]
__device__ unsigned g_X2h[NTRK * 32 * 64];      // conv2 out packed [131072][64w]
__device__ unsigned g_trackH[NTRK * 128];       // [kp_feat | hand_feat] packed [4096][128w]
__device__ float    g_H1[NTRK * 256];           // fc1 out fp32
__device__ unsigned g_vmax[NVID];               // ordered-encoded segment max

// ------------------------- streams/events for graph fork-join (created once, pre-baseline) --
static cudaStream_t g_sB;
static cudaEvent_t g_evF, g_evJ;
namespace {
struct StreamInit {
    StreamInit() {
        cudaStreamCreate(&g_sB);
        cudaEventCreateWithFlags(&g_evF, cudaEventDisableTiming);
        cudaEventCreateWithFlags(&g_evJ, cudaEventDisableTiming);
    }
} s_streamInit;
}

// ------------------------- helpers -------------------------
__device__ __forceinline__ unsigned f2ord(float f) {
    unsigned u = __float_as_uint(f);
    return (u & 0x80000000u) ? ~u : (u | 0x80000000u);
}
__device__ __forceinline__ float ord2f(unsigned u) {
    return __uint_as_float((u & 0x80000000u) ? (u & 0x7fffffffu) : ~u);
}
__device__ __forceinline__ unsigned su32(const void* p) {
    unsigned r;
    asm("{.reg .u64 t; cvta.to.shared.u64 t, %1; cvt.u32.u64 %0, t;}" : "=r"(r) : "l"(p));
    return r;
}
__device__ __forceinline__ void cpa16(unsigned d, const void* s) {
    asm volatile("cp.async.cg.shared.global [%0],[%1],16;" :: "r"(d), "l"(s));
}
__device__ __forceinline__ void cpcommit() { asm volatile("cp.async.commit_group;"); }
__device__ __forceinline__ void cpwait0() { asm volatile("cp.async.wait_group 0;"); }
__device__ __forceinline__ void cpwait1() { asm volatile("cp.async.wait_group 1;"); }
__device__ __forceinline__ void cpwait2() { asm volatile("cp.async.wait_group 2;"); }
__device__ __forceinline__ void mma16h(float* d, const unsigned* a, const unsigned* b) {
    asm volatile(
        "mma.sync.aligned.m16n8k16.row.col.f32.f16.f16.f32 "
        "{%0,%1,%2,%3},{%4,%5,%6,%7},{%8,%9},{%0,%1,%2,%3};"
        : "+f"(d[0]), "+f"(d[1]), "+f"(d[2]), "+f"(d[3])
        : "r"(a[0]), "r"(a[1]), "r"(a[2]), "r"(a[3]), "r"(b[0]), "r"(b[1]));
}
__device__ __forceinline__ unsigned packh2(float lo, float hi) {
    __half2 h = __floats2half2_rn(lo, hi);
    return *reinterpret_cast<unsigned*>(&h);
}
__device__ __forceinline__ float2 unpackh2(unsigned w) {
    return __half22float2(*reinterpret_cast<__half2*>(&w));
}
__device__ __forceinline__ float sigm(float x) { return 1.f / (1.f + __expf(-x)); }

// ------------------------- prep: im2col + weight packing -------------------------
__global__ void prep1(const float* __restrict__ poses,
                      const float* __restrict__ c1w, const float* __restrict__ c2w,
                      const float* __restrict__ wih, const float* __restrict__ whh,
                      const float* __restrict__ bih, const float* __restrict__ bhh,
                      const float* __restrict__ fc1w) {
    const long NPH = (long)NTRK * 32 * 80;
    const long NX1P = (long)NTRK * 2 * 64;
    const long total = NPH + NX1P + 10240 + 24576 + 24576 + 24576 + 384 + 32768 + NVID;
    for (long i = (long)blockIdx.x * blockDim.x + threadIdx.x; i < total;
         i += (long)gridDim.x * blockDim.x) {
        long idx = i;
        if (idx < NPH) {  // im2col poses, fp16 pairs along k (k = kt*51+ci, 160-padded)
            long row = idx / 80;
            int kp = (int)(idx % 80);
            long n = row >> 5;
            int t = (int)(row & 31);
            float v[2];
#pragma unroll
            for (int e = 0; e < 2; e++) {
                int k = 2 * kp + e;
                v[e] = 0.f;
                if (k < 153) {
                    int kt = k / 51, ci = k - kt * 51;
                    int ts = t + kt - 1;
                    if (ts >= 0 && ts < 32) v[e] = poses[(n * 32 + ts) * 51 + ci];
                }
            }
            g_Ph[idx] = packh2(v[0], v[1]);
            continue;
        }
        idx -= NPH;
        if (idx < NX1P) {  // zero X1h pad rows tp=0,33
            long n = idx >> 7;
            int r = (int)(idx & 127);
            int tp = (r < 64) ? 0 : 33;
            g_X1h[n * (34 * 64) + tp * 64 + (r & 63)] = 0u;
            continue;
        }
        idx -= NX1P;
        if (idx < 10240) {  // W1h [kp][co]
            int kp = (int)(idx >> 7), co = (int)(idx & 127);
            float v[2];
#pragma unroll
            for (int e = 0; e < 2; e++) {
                int k = 2 * kp + e;
                v[e] = 0.f;
                if (k < 153) { int kt = k / 51, ci = k - kt * 51; v[e] = c1w[co * 153 + ci * 3 + kt]; }
            }
            g_W1h[idx] = packh2(v[0], v[1]);
            continue;
        }
        idx -= 10240;
        if (idx < 24576) {  // W2h [kp][co], k = kt*128+ci
            int kp = (int)(idx >> 7), co = (int)(idx & 127);
            float v[2];
#pragma unroll
            for (int e = 0; e < 2; e++) {
                int k = 2 * kp + e;
                int kt = k >> 7, ci = k & 127;
                v[e] = c2w[co * 384 + ci * 3 + kt];
            }
            g_W2h[idx] = packh2(v[0], v[1]);
            continue;
        }
        idx -= 24576;
        if (idx < 24576) {  // Wihh [kp][j]
            int kp = (int)(idx / 384), j = (int)(idx % 384);
            g_Wihh[idx] = packh2(wih[j * 128 + 2 * kp], wih[j * 128 + 2 * kp + 1]);
            continue;
        }
        idx -= 24576;
        if (idx < 24576) {  // WhhH [kp][j]
            int kp = (int)(idx / 384), j = (int)(idx % 384);
            g_WhhH[idx] = packh2(whh[j * 128 + 2 * kp], whh[j * 128 + 2 * kp + 1]);
            continue;
        }
        idx -= 24576;
        if (idx < 384) { g_bgi[idx] = bih[idx] + ((idx < 256) ? bhh[idx] : 0.f); continue; }
        idx -= 384;
        if (idx < 32768) {  // fc1h [kp][j]
            int kp = (int)(idx >> 8), j = (int)(idx & 255);
            g_fc1h[idx] = packh2(fc1w[(2 * kp) * 256 + j], fc1w[(2 * kp + 1) * 256 + j]);
            continue;
        }
        idx -= 32768;
        g_vmax[idx] = 0u;
    }
}

// ------------------------- fold img_w @ hand_w -> half2-packed [kp][n] -------------------------
__global__ void __launch_bounds__(256) foldw(const float* __restrict__ img_w,
                                             const float* __restrict__ img_b,
                                             const float* __restrict__ hand_w,
                                             const float* __restrict__ hand_b) {
    __shared__ float simg[64][68];
    __shared__ float shw[64][132];
    __shared__ float sv[512];
    int b = blockIdx.x, tid = threadIdx.x;
    if (b < 16) {
        int tr = tid >> 4;
        int tc = (tid & 15) * 8;
        float acc[4][8];
#pragma unroll
        for (int i = 0; i < 4; i++)
#pragma unroll
            for (int j = 0; j < 8; j++) acc[i][j] = 0.f;
        for (int kt = 0; kt < 512; kt += 64) {
            __syncthreads();
#pragma unroll
            for (int i = 0; i < 4; i++) {
                int ch = tid + i * 256;
                int r = ch >> 4, c4 = (ch & 15) * 4;
                *(float4*)&simg[r][c4] = *(const float4*)&img_w[(long)(b * 64 + r) * 512 + kt + c4];
            }
#pragma unroll
            for (int i = 0; i < 8; i++) {
                int ch = tid + i * 256;
                int r = ch >> 5, c4 = (ch & 31) * 4;
                *(float4*)&shw[r][c4] = *(const float4*)&hand_w[(long)(kt + r) * 128 + c4];
            }
            __syncthreads();
#pragma unroll 8
            for (int q = 0; q < 64; q++) {
                float4 w0 = *(float4*)&shw[q][tc];
                float4 w1 = *(float4*)&shw[q][tc + 4];
#pragma unroll
                for (int i = 0; i < 4; i++) {
                    float a = simg[tr * 4 + i][q];
                    acc[i][0] += a * w0.x; acc[i][1] += a * w0.y;
                    acc[i][2] += a * w0.z; acc[i][3] += a * w0.w;
                    acc[i][4] += a * w1.x; acc[i][5] += a * w1.y;
                    acc[i][6] += a * w1.z; acc[i][7] += a * w1.w;
                }
            }
        }
        int kp0 = (b * 64 + tr * 4) >> 1;
#pragma unroll
        for (int j = 0; j < 8; j++) {
            g_WhandH[(kp0) * 128 + tc + j]     = packh2(acc[0][j], acc[1][j]);
            g_WhandH[(kp0 + 1) * 128 + tc + j] = packh2(acc[2][j], acc[3][j]);
        }
    } else {
        for (int q = tid; q < 512; q += 256) sv[q] = img_b[q];
        __syncthreads();
        if (tid < 128) {
            float a = hand_b[tid];
#pragma unroll 8
            for (int q = 0; q < 512; q++) a += sv[q] * hand_w[q * 128 + tid];
            g_bhand[tid] = a;
        }
    }
}

// ------------------------- unified fp16 GEMM (A and B half2-packed along K) ------------------
template <int ARPG, int ORPG, int MODE, bool RELU>
__global__ void __launch_bounds__(256) gemm_h(
    const unsigned* __restrict__ A, long aGS, long aRS, long aOfs,
    const unsigned* __restrict__ Bm, int ldb,
    const float* __restrict__ bias,
    void* __restrict__ CoutV, long oGS, long oRS, long oOfs,
    int K) {
    constexpr int SAST = 20, SBST = 136;
    constexpr int ASZ = 128 * SAST, BSZ = 16 * SBST;
    extern __shared__ unsigned smu[];
    unsigned* sA = smu;
    unsigned* sB = smu + 2 * ASZ;

    const int tid = threadIdx.x, lane = tid & 31, wid = tid >> 5;
    const int wm = wid & 3, wn = wid >> 2;
    const int g = lane >> 2, t2 = lane & 3;
    const long m0 = (long)blockIdx.x * 128;
    const int n0 = blockIdx.y * 128;

    float acc[2][8][4];
#pragma unroll
    for (int i = 0; i < 2; i++)
#pragma unroll
        for (int j = 0; j < 8; j++)
#pragma unroll
            for (int q = 0; q < 4; q++) acc[i][j][q] = 0.f;

    const unsigned* aP[2];
    unsigned aD[2];
#pragma unroll
    for (int i = 0; i < 2; i++) {
        int ch = tid + i * 256;
        int row = ch >> 2, cw = (ch & 3) * 4;
        long gr = m0 + row;
        const unsigned* rp = ARPG ? (A + (gr / ARPG) * aGS + (gr % ARPG) * aRS + aOfs)
                                  : (A + gr * aRS + aOfs);
        aP[i] = rp + cw;
        aD[i] = su32(sA) + (unsigned)((row * SAST + cw) * 4);
    }
    const unsigned* bP[2];
    unsigned bD[2];
#pragma unroll
    for (int i = 0; i < 2; i++) {
        int ch = tid + i * 256;
        int row = ch >> 5, cw = (ch & 31) * 4;
        bP[i] = Bm + (long)row * ldb + n0 + cw;
        bD[i] = su32(sB) + (unsigned)((row * SBST + cw) * 4);
    }

    auto load = [&](int buf, int s) {
#pragma unroll
        for (int i = 0; i < 2; i++) cpa16(aD[i] + (unsigned)buf * ASZ * 4, aP[i] + s * 16);
#pragma unroll
        for (int i = 0; i < 2; i++) cpa16(bD[i] + (unsigned)buf * BSZ * 4, bP[i] + (long)s * 16 * ldb);
        cpcommit();
    };

    const int NS = K / 32;
    load(0, 0);
    for (int s = 0; s < NS; s++) {
        if (s + 1 < NS) { load((s + 1) & 1, s + 1); cpwait1(); }
        else cpwait0();
        __syncthreads();
        const unsigned* cA = sA + (s & 1) * ASZ;
        const unsigned* cB = sB + (s & 1) * BSZ;
#pragma unroll
        for (int kk2 = 0; kk2 < 2; kk2++) {
            unsigned af[2][4];
            const int r0 = wm * 32 + g, kc = kk2 * 8 + t2;
#pragma unroll
            for (int i = 0; i < 2; i++) {
                af[i][0] = cA[(r0 + i * 16) * SAST + kc];
                af[i][1] = cA[(r0 + i * 16 + 8) * SAST + kc];
                af[i][2] = cA[(r0 + i * 16) * SAST + kc + 4];
                af[i][3] = cA[(r0 + i * 16 + 8) * SAST + kc + 4];
            }
#pragma unroll
            for (int j = 0; j < 8; j++) {
                unsigned bf[2];
                int bc = wn * 64 + j * 8 + g;
                bf[0] = cB[kc * SBST + bc];
                bf[1] = cB[(kc + 4) * SBST + bc];
                mma16h(acc[0][j], af[0], bf);
                mma16h(acc[1][j], af[1], bf);
            }
        }
        __syncthreads();
    }

#pragma unroll
    for (int i = 0; i < 2; i++)
#pragma unroll
        for (int j = 0; j < 8; j++)
#pragma unroll
            for (int h = 0; h < 2; h++) {
                long gr = m0 + wm * 32 + i * 16 + h * 8 + g;
                int col = n0 + wn * 64 + j * 8 + t2 * 2;
                float v0 = acc[i][j][h * 2 + 0] + bias[col];
                float v1 = acc[i][j][h * 2 + 1] + bias[col + 1];
                if (RELU) { v0 = fmaxf(v0, 0.f); v1 = fmaxf(v1, 0.f); }
                if (MODE == 0) {
                    float* O = (float*)CoutV;
                    float* op = ORPG ? (O + (gr / ORPG) * oGS + (gr % ORPG) * oRS + oOfs + col)
                                     : (O + gr * oRS + oOfs + col);
                    ((float2*)op)[0] = make_float2(v0, v1);
                } else {
                    unsigned* O = (unsigned*)CoutV;
                    int wc = col >> 1;
                    unsigned* op = ORPG ? (O + (gr / ORPG) * oGS + (gr % ORPG) * oRS + oOfs + wc)
                                        : (O + gr * oRS + oOfs + wc);
                    *op = packh2(v0, v1);
                }
            }
}

// ------------------------- hand GEMM: R10 structure + 3-stage cp.async pipeline -------------
#define HH_SAST 40
#define HH_SBST 136
#define HH_ASZ  (128 * HH_SAST)
#define HH_BSZ  (16 * HH_SBST)
#define HH_SMEM ((3 * HH_ASZ + 3 * HH_BSZ + 4 * 132) * 4)

__global__ void __launch_bounds__(256) hand_h(
    const float* __restrict__ hands,
    const unsigned* __restrict__ Bh,
    const float* __restrict__ bias,
    unsigned* __restrict__ trackH) {
    extern __shared__ float sm[];
    float* sA = sm;
    unsigned* sB = (unsigned*)(sm + 3 * HH_ASZ);
    float* mst = sm + 3 * HH_ASZ + 3 * HH_BSZ;

    const int tid = threadIdx.x, lane = tid & 31, wid = tid >> 5;
    const int wm = wid & 3, wn = wid >> 2;
    const long m0 = (long)blockIdx.x * 128;
    const int g = lane >> 2, t2 = lane & 3;

    float acc[2][8][4];
#pragma unroll
    for (int i = 0; i < 2; i++)
#pragma unroll
        for (int j = 0; j < 8; j++)
#pragma unroll
            for (int q = 0; q < 4; q++) acc[i][j][q] = 0.f;

    const float* aP[4];
    unsigned aD[4];
#pragma unroll
    for (int i = 0; i < 4; i++) {
        int ch = tid + i * 256;
        int row = ch >> 3, c4 = (ch & 7) * 4;
        aP[i] = hands + (m0 + row) * 1024 + c4;
        aD[i] = su32(sA) + (unsigned)((row * HH_SAST + c4) * 4);
    }
    const unsigned* bP[2];
    unsigned bD[2];
#pragma unroll
    for (int i = 0; i < 2; i++) {
        int ch = tid + i * 256;
        int row = ch >> 5, c4 = (ch & 31) * 4;
        bP[i] = Bh + row * 128 + c4;
        bD[i] = su32(sB) + (unsigned)((row * HH_SBST + c4) * 4);
    }

    auto load = [&](int buf, int s) {
#pragma unroll
        for (int i = 0; i < 4; i++) cpa16(aD[i] + (unsigned)buf * HH_ASZ * 4, aP[i] + s * 32);
#pragma unroll
        for (int i = 0; i < 2; i++) cpa16(bD[i] + (unsigned)buf * HH_BSZ * 4, bP[i] + s * 16 * 128);
        cpcommit();
    };

    // 3-stage pipeline: keep up to 2 stages in flight beyond the one being consumed
    load(0, 0);
    load(1, 1);
    for (int s = 0; s < 32; s++) {
        if (s + 2 < 32) { load((s + 2) % 3, s + 2); cpwait2(); }
        else if (s + 1 < 32) cpwait1();
        else cpwait0();
        __syncthreads();
        const float* cA = sA + (s % 3) * HH_ASZ;
        const unsigned* cB = sB + (s % 3) * HH_BSZ;
#pragma unroll
        for (int kk2 = 0; kk2 < 2; kk2++) {
            const int c = kk2 * 16 + t2 * 2;
            unsigned af[2][4];
#pragma unroll
            for (int i = 0; i < 2; i++) {
                int r = wm * 32 + g + i * 16;
                float2 v0 = *(const float2*)(cA + r * HH_SAST + c);
                float2 v1 = *(const float2*)(cA + (r + 8) * HH_SAST + c);
                float2 v2 = *(const float2*)(cA + r * HH_SAST + c + 8);
                float2 v3 = *(const float2*)(cA + (r + 8) * HH_SAST + c + 8);
                af[i][0] = packh2(v0.x, v0.y);
                af[i][1] = packh2(v1.x, v1.y);
                af[i][2] = packh2(v2.x, v2.y);
                af[i][3] = packh2(v3.x, v3.y);
            }
            const int kp0 = kk2 * 8 + t2;
            const int bc = wn * 64 + g;
#pragma unroll
            for (int j = 0; j < 8; j++) {
                unsigned bf[2];
                bf[0] = cB[kp0 * HH_SBST + bc + j * 8];
                bf[1] = cB[(kp0 + 4) * HH_SBST + bc + j * 8];
                mma16h(acc[0][j], af[0], bf);
                mma16h(acc[1][j], af[1], bf);
            }
        }
        __syncthreads();
    }

    float mc[8][2];
#pragma unroll
    for (int j = 0; j < 8; j++) {
        mc[j][0] = fmaxf(fmaxf(acc[0][j][0], acc[0][j][2]), fmaxf(acc[1][j][0], acc[1][j][2]));
        mc[j][1] = fmaxf(fmaxf(acc[0][j][1], acc[0][j][3]), fmaxf(acc[1][j][1], acc[1][j][3]));
    }
#pragma unroll
    for (int ofs = 4; ofs < 32; ofs <<= 1)
#pragma unroll
        for (int j = 0; j < 8; j++) {
            mc[j][0] = fmaxf(mc[j][0], __shfl_xor_sync(0xffffffffu, mc[j][0], ofs));
            mc[j][1] = fmaxf(mc[j][1], __shfl_xor_sync(0xffffffffu, mc[j][1], ofs));
        }
    if (lane < 4) {
#pragma unroll
        for (int j = 0; j < 8; j++) {
            int col = wn * 64 + j * 8 + lane * 2;
            mst[wm * 132 + col] = mc[j][0];
            mst[wm * 132 + col + 1] = mc[j][1];
        }
    }
    __syncthreads();
    {
        int sub = tid & 127;
        if (sub < 64) {
            int trk2 = tid >> 7, wc = sub;
            float v0 = fmaxf(mst[(trk2 * 2) * 132 + 2 * wc], mst[(trk2 * 2 + 1) * 132 + 2 * wc]);
            float v1 = fmaxf(mst[(trk2 * 2) * 132 + 2 * wc + 1], mst[(trk2 * 2 + 1) * 132 + 2 * wc + 1]);
            long track = (long)blockIdx.x * 2 + trk2;
            trackH[track * 128 + 64 + wc] = packh2(v0 + bias[2 * wc], v1 + bias[2 * wc + 1]);
        }
    }
}

// ------------------------- fused GRU+gi: Whh AND Wih resident, x_t streamed, 1 launch --------
#define GR_WST 392
#define GR_HST 68
#define GR_SMEM ((2 * 64 * GR_WST + 3 * 32 * GR_HST) * 4)

__global__ void __launch_bounds__(256) gru_fused(
    const unsigned* __restrict__ whhH,
    const unsigned* __restrict__ wihH,
    const unsigned* __restrict__ x2h,
    const float* __restrict__ bgi,
    const float* __restrict__ bhhn,
    unsigned* __restrict__ trackH) {
    extern __shared__ unsigned smg[];
    unsigned* sWhh = smg;
    unsigned* sWih = smg + 64 * GR_WST;
    unsigned* sh   = smg + 2 * 64 * GR_WST;
    unsigned* sx   = sh + 32 * GR_HST;
    const int tid = threadIdx.x, lane = tid & 31, w = tid >> 5;
    const int m0 = blockIdx.x * 32;
    const int g = lane >> 2, t2 = lane & 3, cb = t2 * 2;

    {
        unsigned b1 = su32(sWhh), b2 = su32(sWih);
#pragma unroll
        for (int i = 0; i < 24; i++) {
            int ch = tid + i * 256;
            int row = ch / 96, cx = (ch % 96) * 4;
            cpa16(b1 + (unsigned)((row * GR_WST + cx) * 4), whhH + row * 384 + cx);
            cpa16(b2 + (unsigned)((row * GR_WST + cx) * 4), wihH + row * 384 + cx);
        }
#pragma unroll
        for (int i = 0; i < 2; i++) {
            int ch = tid + i * 256;
            int row = ch >> 4, c4 = (ch & 15) * 4;
            cpa16(su32(sx) + (unsigned)((row * GR_HST + c4) * 4),
                  x2h + ((long)(m0 + row) * 32) * 64 + c4);
        }
        cpcommit();
    }
    for (int i = tid; i < 32 * GR_HST; i += 256) sh[i] = 0u;
    cpwait0();
    __syncthreads();

    float br[2][2], bz[2][2], bni[2][2], bn[2][2];
#pragma unroll
    for (int jj = 0; jj < 2; jj++) {
        int c = w * 16 + jj * 8 + cb;
        br[jj][0] = bgi[c];        br[jj][1] = bgi[c + 1];
        bz[jj][0] = bgi[128 + c];  bz[jj][1] = bgi[128 + c + 1];
        bni[jj][0] = bgi[256 + c]; bni[jj][1] = bgi[256 + c + 1];
        bn[jj][0] = bhhn[c];       bn[jj][1] = bhhn[c + 1];
    }

    for (int step = 0; step < 32; step++) {
        if (step < 31) {
            unsigned dst = su32(sx) + (unsigned)(((step + 1) & 1) * 32 * GR_HST * 4);
#pragma unroll
            for (int i = 0; i < 2; i++) {
                int ch = tid + i * 256;
                int row = ch >> 4, c4 = (ch & 15) * 4;
                cpa16(dst + (unsigned)((row * GR_HST + c4) * 4),
                      x2h + ((long)(m0 + row) * 32 + step + 1) * 64 + c4);
            }
            cpcommit();
        }
        float acc[8][2][4];
#pragma unroll
        for (int f = 0; f < 8; f++)
#pragma unroll
            for (int i = 0; i < 2; i++)
#pragma unroll
                for (int q = 0; q < 4; q++) acc[f][i][q] = 0.f;

        const unsigned* cx = sx + (step & 1) * 32 * GR_HST;
#pragma unroll
        for (int ch = 0; ch < 8; ch++) {
            unsigned afh[2][4], afx[2][4];
            const int kc = ch * 8 + t2;
#pragma unroll
            for (int i = 0; i < 2; i++) {
                int r = i * 16 + g;
                afh[i][0] = sh[r * GR_HST + kc];
                afh[i][1] = sh[(r + 8) * GR_HST + kc];
                afh[i][2] = sh[r * GR_HST + kc + 4];
                afh[i][3] = sh[(r + 8) * GR_HST + kc + 4];
                afx[i][0] = cx[r * GR_HST + kc];
                afx[i][1] = cx[(r + 8) * GR_HST + kc];
                afx[i][2] = cx[r * GR_HST + kc + 4];
                afx[i][3] = cx[(r + 8) * GR_HST + kc + 4];
            }
#pragma unroll
            for (int gg = 0; gg < 3; gg++)
#pragma unroll
                for (int jj = 0; jj < 2; jj++) {
                    int col = gg * 128 + w * 16 + jj * 8 + g;
                    unsigned bfh[2], bfx[2];
                    bfh[0] = sWhh[kc * GR_WST + col];
                    bfh[1] = sWhh[(kc + 4) * GR_WST + col];
                    bfx[0] = sWih[kc * GR_WST + col];
                    bfx[1] = sWih[(kc + 4) * GR_WST + col];
                    int hg = gg * 2 + jj;
                    int xg = (gg < 2) ? hg : (6 + jj);
                    mma16h(acc[hg][0], afh[0], bfh);
                    mma16h(acc[hg][1], afh[1], bfh);
                    mma16h(acc[xg][0], afx[0], bfx);
                    mma16h(acc[xg][1], afx[1], bfx);
                }
        }
        __syncthreads();

#pragma unroll
        for (int i = 0; i < 2; i++)
#pragma unroll
            for (int rh = 0; rh < 2; rh++) {
                int row = g + i * 16 + rh * 8;
                int q = rh * 2;
#pragma unroll
                for (int jj = 0; jj < 2; jj++) {
                    int wc = (w * 16 + jj * 8 + cb) >> 1;
                    float2 hold = unpackh2(sh[row * GR_HST + wc]);
                    float r0 = sigm(acc[jj][i][q] + br[jj][0]);
                    float r1 = sigm(acc[jj][i][q + 1] + br[jj][1]);
                    float z0 = sigm(acc[2 + jj][i][q] + bz[jj][0]);
                    float z1 = sigm(acc[2 + jj][i][q + 1] + bz[jj][1]);
                    float n0 = tanhf(acc[6 + jj][i][q] + bni[jj][0] + r0 * (acc[4 + jj][i][q] + bn[jj][0]));
                    float n1 = tanhf(acc[6 + jj][i][q + 1] + bni[jj][1] + r1 * (acc[4 + jj][i][q + 1] + bn[jj][1]));
                    float h0 = (1.f - z0) * n0 + z0 * hold.x;
                    float h1 = (1.f - z1) * n1 + z1 * hold.y;
                    sh[row * GR_HST + wc] = packh2(h0, h1);
                }
            }
        cpwait0();
        __syncthreads();
    }

#pragma unroll
    for (int it = 0; it < 8; it++) {
        int idx = it * 256 + tid;
        int row = idx >> 6, wc = idx & 63;
        trackH[(long)(m0 + row) * 128 + wc] = sh[row * GR_HST + wc];
    }
}

// ------------------------- small kernels -------------------------
__global__ void fc2seg(const float* __restrict__ w, const float* __restrict__ b2,
                       const int* __restrict__ vidx) {
    __shared__ float sw[256];
    int t = threadIdx.x;
    sw[t] = w[t];
    __syncthreads();
    int m = blockIdx.x * 256 + t;
    const float* h = &g_H1[(long)m * 256];
    float a = b2[0];
#pragma unroll 16
    for (int q = 0; q < 256; q++) a += h[q] * sw[q];
    atomicMax(&g_vmax[vidx[m]], f2ord(a));
}

__global__ void finalk(const float* __restrict__ nts, float* __restrict__ out) {
    int v = blockIdx.x * 256 + threadIdx.x;
    if (v < NVID) {
        unsigned u = g_vmax[v];
        float lg = (u == 0u) ? nts[0] : ord2f(u);
        out[v] = 1.f / (1.f + expf(-lg));
    }
}

// ------------------------- launch -------------------------
extern "C" void kernel_launch(void* const* d_in, const int* in_sizes, int n_in,
                              void* d_out, int out_size) {
    const float* poses  = (const float*)d_in[0];
    const float* hands  = (const float*)d_in[1];
    const int*   vidx   = (const int*)d_in[2];
    const float* c1w    = (const float*)d_in[3];
    const float* c1b    = (const float*)d_in[4];
    const float* c2w    = (const float*)d_in[5];
    const float* c2b    = (const float*)d_in[6];
    const float* wih    = (const float*)d_in[7];
    const float* whh    = (const float*)d_in[8];
    const float* bih    = (const float*)d_in[9];
    const float* bhh    = (const float*)d_in[10];
    const float* img_w  = (const float*)d_in[11];
    const float* img_b  = (const float*)d_in[12];
    const float* hand_w = (const float*)d_in[13];
    const float* hand_b = (const float*)d_in[14];
    const float* fc1w   = (const float*)d_in[15];
    const float* fc1b   = (const float*)d_in[16];
    const float* fc2w   = (const float*)d_in[17];
    const float* fc2b   = (const float*)d_in[18];
    const float* nts    = (const float*)d_in[19];
    float* out = (float*)d_out;

    unsigned *pPh, *pW1h, *pW2h, *pWihh, *pWhhH, *pWhandH, *pfc1h, *pX1h, *pX2h, *pTrackH;
    float *pbgi, *pbhand, *pH1;
    cudaGetSymbolAddress((void**)&pPh, g_Ph);
    cudaGetSymbolAddress((void**)&pW1h, g_W1h);
    cudaGetSymbolAddress((void**)&pW2h, g_W2h);
    cudaGetSymbolAddress((void**)&pWihh, g_Wihh);
    cudaGetSymbolAddress((void**)&pWhhH, g_WhhH);
    cudaGetSymbolAddress((void**)&pbgi, g_bgi);
    cudaGetSymbolAddress((void**)&pWhandH, g_WhandH);
    cudaGetSymbolAddress((void**)&pbhand, g_bhand);
    cudaGetSymbolAddress((void**)&pfc1h, g_fc1h);
    cudaGetSymbolAddress((void**)&pX1h, g_X1h);
    cudaGetSymbolAddress((void**)&pX2h, g_X2h);
    cudaGetSymbolAddress((void**)&pTrackH, g_trackH);
    cudaGetSymbolAddress((void**)&pH1, g_H1);

    constexpr int SM_H = (2 * 128 * 20 + 2 * 16 * 136) * 4;     // 37888 B

    auto* kConv1 = gemm_h<0, 32, 1, true>;
    auto* kConv2 = gemm_h<32, 0, 1, true>;
    auto* kFc1   = gemm_h<0, 0, 0, true>;

    cudaFuncSetAttribute(kConv1, cudaFuncAttributeMaxDynamicSharedMemorySize, SM_H);
    cudaFuncSetAttribute(kConv2, cudaFuncAttributeMaxDynamicSharedMemorySize, SM_H);
    cudaFuncSetAttribute(kFc1, cudaFuncAttributeMaxDynamicSharedMemorySize, SM_H);
    cudaFuncSetAttribute(gru_fused, cudaFuncAttributeMaxDynamicSharedMemorySize, GR_SMEM);
    cudaFuncSetAttribute(hand_h, cudaFuncAttributeMaxDynamicSharedMemorySize, HH_SMEM);

    // ---- fork: hand path on g_sB, pose chain on default stream ----
    cudaEventRecord(g_evF, 0);
    cudaStreamWaitEvent(g_sB, g_evF, 0);

    foldw<<<17, 256, 0, g_sB>>>(img_w, img_b, hand_w, hand_b);
    hand_h<<<2048, 256, HH_SMEM, g_sB>>>(hands, pWhandH, pbhand, pTrackH);
    cudaEventRecord(g_evJ, g_sB);

    // default stream: pose chain (gi fused into GRU; no GIh round-trip)
    prep1<<<4096, 256>>>(poses, c1w, c2w, wih, whh, bih, bhh, fc1w);
    kConv1<<<dim3(1024, 1), 256, SM_H>>>(pPh, 0, 80, 0, pW1h, 128, c1b,
                                         pX1h, 34 * 64, 64, 64, 160);
    kConv2<<<dim3(1024, 1), 256, SM_H>>>(pX1h, 34 * 64, 64, 0, pW2h, 128, c2b,
                                         pX2h, 0, 64, 0, 384);
    gru_fused<<<128, 256, GR_SMEM>>>(pWhhH, pWihh, pX2h, pbgi, bhh + 256, pTrackH);

    // ---- join, then scoring ----
    cudaStreamWaitEvent(0, g_evJ, 0);
    kFc1<<<dim3(32, 2), 256, SM_H>>>(pTrackH, 0, 128, 0, pfc1h, 256, fc1b,
                                     pH1, 0, 256, 0, 256);
    fc2seg<<<16, 256>>>(fc2w, fc2b, vidx);
    finalk<<<2, 256>>>(nts, out);
}